// round 10
// baseline (speedup 1.0000x reference)
#include <cuda_runtime.h>
#include <cstdint>

#define TN 2048
#define BN 256
#define DN 40
#define HN 128
#define CN 35
#define TDN (TN * DN)
#define NCTA 256
#define NTHR 128
#define GB   32     // batch rows per group

// ---------------------------------------------------------------------------
// Persistent device scratch.
__device__ __align__(16) float g_xT[TDN * BN];     // x transposed: [t*D + d][b]
__device__ __align__(16) float g_h0[2][HN * BN];   // layer0 h double buffer, [k][b]
__device__ __align__(16) float g_h1[2][HN * BN];   // layer1 h double buffer, [k][b]

struct alignas(128) BarSlot { unsigned v; };
__device__ BarSlot g_cnt;                          // full-grid barrier (rare)
__device__ volatile BarSlot g_phz;                 // monotonic phase
__device__ __align__(128) unsigned g_flag[8][32];  // [group][ublock] step counters

// ---------------------------------------------------------------------------
union F2U { float2 f; unsigned long long u; };
__device__ __forceinline__ void ffma2(float2& acc, float2 a, float2 b) {
    F2U ua, ub, uc;
    ua.f = a; ub.f = b; uc.f = acc;
    asm("fma.rn.f32x2 %0, %1, %2, %0;" : "+l"(uc.u) : "l"(ua.u), "l"(ub.u));
    acc = uc.f;
}
__device__ __forceinline__ float sigf(float x)  { return 1.0f / (1.0f + __expf(-x)); }
__device__ __forceinline__ float tanhx(float x) {
    x = fminf(fmaxf(x, -15.f), 15.f);
    float e = __expf(2.f * x);
    return (e - 1.f) / (e + 1.f);
}
__device__ __forceinline__ unsigned ldacq(const unsigned* p) {
    unsigned v;
    asm volatile("ld.acquire.gpu.global.u32 %0, [%1];" : "=r"(v) : "l"(p) : "memory");
    return v;
}
__device__ __forceinline__ void strel(unsigned* p, unsigned v) {
    asm volatile("st.release.gpu.global.u32 [%0], %1;" :: "l"(p), "r"(v) : "memory");
}

// Full-grid barrier (twice per launch; monotonic phase survives replays).
__device__ __forceinline__ void gbar_full() {
    __syncthreads();
    if (threadIdx.x == 0) {
        unsigned ph = g_phz.v;
        __threadfence();
        if (atomicAdd(&g_cnt.v, 1u) == NCTA - 1u) {
            g_cnt.v = 0u;
            __threadfence();
            g_phz.v = ph + 1u;
        } else {
            while (g_phz.v == ph) { }
            __threadfence();
        }
    }
    __syncthreads();
}

// ---------------------------------------------------------------------------
// SMEM (~64 KB dynamic -> 2 CTAs/SM). Weights gate-pair packed:
// w[u][k] as float4 {Wi, Wf, Wg, Wo}.
struct alignas(16) SmemLayout {
    float2 wx [4][DN][2];    // L0 W_ih   (2.5 KB)
    float2 wh0[4][HN][2];    // L0 W_hh   (8 KB)
    float2 w1i[4][HN][2];    // L1 W_ih   (8 KB)
    float2 w1h[4][HN][2];    // L1 W_hh   (8 KB)
    float2 sb[2][4][2];      // bias pairs
    float  sx [DN * GB];     // staged x tile          (5 KB)
    float  sh0[HN * GB];     // staged h0(it-1) tile   (16 KB) — both layers
    float  sh1[HN * GB];     // staged h1(it-2) tile   (16 KB)
};
#define SMEM_BYTES ((int)sizeof(SmemLayout))

struct LstmArgs {
    const float *x;
    const int   *length;
    const float *Wih0, *Whh0, *bih0, *bhh0;
    const float *Wih1, *Whh1, *bih1, *bhh1;
    const float *lng, *lnb, *fcw, *fcb;
    float       *out;
};

// MAC over K rows for 2 units against a staged [k][GB] tile.
__device__ __forceinline__ void mac_seg(
    float2& aif0, float2& ago0, float2& aif1, float2& ago1,
    const float4* __restrict__ w0, const float4* __restrict__ w1,
    const float* __restrict__ sv, int K)
{
#pragma unroll 4
    for (int k = 0; k < K; k++) {
        float v  = sv[k << 5];               // stride GB=32, conflict-free
        float2 d = make_float2(v, v);
        float4 wa = w0[k];
        ffma2(aif0, make_float2(wa.x, wa.y), d);
        ffma2(ago0, make_float2(wa.z, wa.w), d);
        float4 wb = w1[k];
        ffma2(aif1, make_float2(wb.x, wb.y), d);
        ffma2(ago1, make_float2(wb.z, wb.w), d);
    }
}

// ---------------------------------------------------------------------------
// Single persistent kernel. CTA = 4 units (both layers) x 32 batch rows,
// 128 threads = 4 warps: (s = layer, up = unit pair), lane = batch row.
__global__ void __launch_bounds__(NTHR, 2) lstm_kernel(LstmArgs a) {
    extern __shared__ char smem_raw[];
    SmemLayout* sm = (SmemLayout*)smem_raw;
    const int bid = blockIdx.x;
    const int tid = threadIdx.x;

    const int ub    = bid >> 3;       // 0..31 : unit block (4 units)
    const int grp   = bid & 7;        // 0..7  : batch group (32 rows)
    const int u0    = ub * 4;
    const int bbase = grp * GB;

    // ---- phase 0: transpose x, zero state + flags, pack weights ----
    {
        float (*tile)[33] = (float(*)[33])sm->sh0;
        const int tx = tid & 31, ty = tid >> 5;   // 32 x 4
        const int ntile = (TDN / 32) * (BN / 32); // 20480
        for (int tl = bid; tl < ntile; tl += NCTA) {
            int tdBase = (tl % (TDN / 32)) * 32;
            int bBase  = (tl / (TDN / 32)) * 32;
#pragma unroll
            for (int j = 0; j < 8; j++)
                tile[ty + j * 4][tx] =
                    a.x[(size_t)(bBase + ty + j * 4) * TDN + tdBase + tx];
            __syncthreads();
#pragma unroll
            for (int j = 0; j < 8; j++)
                g_xT[(size_t)(tdBase + ty + j * 4) * BN + bBase + tx] =
                    tile[tx][ty + j * 4];
            __syncthreads();
        }
        for (int i = bid * NTHR + tid; i < HN * BN; i += NCTA * NTHR) {
            g_h0[0][i] = 0.f; g_h0[1][i] = 0.f;
            g_h1[0][i] = 0.f; g_h1[1][i] = 0.f;
        }
        if (bid == 0)
            for (int i = tid; i < 8 * 32; i += NTHR)
                *((volatile unsigned*)&g_flag[0][0] + i) = 0u;

        // weight packing (one-time)
        for (int i = tid; i < 4 * DN; i += NTHR) {
            int u = i / DN, k = i - u * DN, r = u0 + u;
            sm->wx[u][k][0] = make_float2(a.Wih0[(0 * HN + r) * DN + k],
                                          a.Wih0[(1 * HN + r) * DN + k]);
            sm->wx[u][k][1] = make_float2(a.Wih0[(2 * HN + r) * DN + k],
                                          a.Wih0[(3 * HN + r) * DN + k]);
        }
        for (int i = tid; i < 4 * HN; i += NTHR) {
            int u = i >> 7, k = i & 127, r = u0 + u;
            sm->wh0[u][k][0] = make_float2(a.Whh0[(0 * HN + r) * HN + k],
                                           a.Whh0[(1 * HN + r) * HN + k]);
            sm->wh0[u][k][1] = make_float2(a.Whh0[(2 * HN + r) * HN + k],
                                           a.Whh0[(3 * HN + r) * HN + k]);
            sm->w1i[u][k][0] = make_float2(a.Wih1[(0 * HN + r) * HN + k],
                                           a.Wih1[(1 * HN + r) * HN + k]);
            sm->w1i[u][k][1] = make_float2(a.Wih1[(2 * HN + r) * HN + k],
                                           a.Wih1[(3 * HN + r) * HN + k]);
            sm->w1h[u][k][0] = make_float2(a.Whh1[(0 * HN + r) * HN + k],
                                           a.Whh1[(1 * HN + r) * HN + k]);
            sm->w1h[u][k][1] = make_float2(a.Whh1[(2 * HN + r) * HN + k],
                                           a.Whh1[(3 * HN + r) * HN + k]);
        }
        if (tid < 16) {
            int s = tid >> 3, u = (tid >> 1) & 3, gp = tid & 1, r = u0 + u;
            const float* bi = s ? a.bih1 : a.bih0;
            const float* bh = s ? a.bhh1 : a.bhh0;
            int g0 = gp * 2, g1 = gp * 2 + 1;
            sm->sb[s][u][gp] = make_float2(bi[g0 * HN + r] + bh[g0 * HN + r],
                                           bi[g1 * HN + r] + bh[g1 * HN + r]);
        }
    }
    gbar_full();

    // ---- phase 1: fused 2-layer step loop ----
    {
        const int wid  = tid >> 5;
        const int lane = tid & 31;
        const int s    = wid >> 1;          // 0: layer0, 1: layer1
        const int up   = wid & 1;           // unit pair
        const int lu0  = up * 2;
        const int b    = bbase + lane;
        const int len  = a.length[b];

        const float4* wp1u0 = s ? (const float4*)&sm->w1i[lu0][0][0]
                                : (const float4*)&sm->wx [lu0][0][0];
        const float4* wp1u1 = s ? (const float4*)&sm->w1i[lu0 + 1][0][0]
                                : (const float4*)&sm->wx [lu0 + 1][0][0];
        const float4* wp2u0 = s ? (const float4*)&sm->w1h[lu0][0][0]
                                : (const float4*)&sm->wh0[lu0][0][0];
        const float4* wp2u1 = s ? (const float4*)&sm->w1h[lu0 + 1][0][0]
                                : (const float4*)&sm->wh0[lu0 + 1][0][0];
        const float* in1 = s ? sm->sh0 : sm->sx;
        const float* in2 = s ? sm->sh1 : sm->sh0;
        const int K1 = s ? HN : DN;

        float c0 = 0.f, c1 = 0.f, hr0 = 0.f, hr1 = 0.f;

#pragma unroll 1
        for (int it = 0; it <= TN; it++) {
            // stage x tile (static input: issue before the flag wait)
            if (it < TN) {
                const float* xsrc = g_xT + (size_t)it * DN * BN + bbase;
                for (int i = tid; i < DN * 8; i += NTHR) {
                    int r = i >> 3, j = (i & 7) << 2;
                    *(float4*)(sm->sx + r * GB + j) =
                        __ldcg((const float4*)(xsrc + (size_t)r * BN + j));
                }
            }
            // wait: all 32 ublock CTAs of this group posted superstep it-1
            if (tid < 32)
                while (ldacq(&g_flag[grp][tid]) < (unsigned)it) { }
            __syncthreads();

            // stage h0(it-1) (shared by both layers) and h1(it-2)
            {
                const float* s0 = g_h0[(it + 1) & 1] + bbase;
                const float* s1 = g_h1[it & 1] + bbase;
                for (int i = tid; i < HN * 8; i += NTHR) {
                    int r = i >> 3, j = (i & 7) << 2;
                    *(float4*)(sm->sh0 + r * GB + j) =
                        __ldcg((const float4*)(s0 + (size_t)r * BN + j));
                    *(float4*)(sm->sh1 + r * GB + j) =
                        __ldcg((const float4*)(s1 + (size_t)r * BN + j));
                }
            }
            __syncthreads();

            const bool active = s ? (it >= 1) : (it < TN);
            if (active) {
                float2 aif0 = sm->sb[s][lu0][0],     ago0 = sm->sb[s][lu0][1];
                float2 aif1 = sm->sb[s][lu0 + 1][0], ago1 = sm->sb[s][lu0 + 1][1];

                mac_seg(aif0, ago0, aif1, ago1, wp1u0, wp1u1, in1 + lane, K1);
                mac_seg(aif0, ago0, aif1, ago1, wp2u0, wp2u1, in2 + lane, HN);

                const int t = s ? (it - 1) : it;
                {
                    float i_ = sigf(aif0.x), f_ = sigf(aif0.y);
                    float g_ = tanhx(ago0.x), o_ = sigf(ago0.y);
                    float cn = f_ * c0 + i_ * g_;
                    float hn = o_ * tanhx(cn);
                    if (t < len) { c0 = cn; hr0 = hn; }
                }
                {
                    float i_ = sigf(aif1.x), f_ = sigf(aif1.y);
                    float g_ = tanhx(ago1.x), o_ = sigf(ago1.y);
                    float cn = f_ * c1 + i_ * g_;
                    float hn = o_ * tanhx(cn);
                    if (t < len) { c1 = cn; hr1 = hn; }
                }
                float* hout = s ? g_h1[(it + 1) & 1] : g_h0[it & 1];
                __stcg(&hout[(size_t)(u0 + lu0) * BN + b], hr0);
                __stcg(&hout[(size_t)(u0 + lu0 + 1) * BN + b], hr1);
            }
            __syncthreads();
            if (tid == 0) {
                __threadfence();
                strel(&g_flag[grp][ub], (unsigned)(it + 1));
            }
        }
    }
    gbar_full();

    // ---- phase 2: LN + FC head (1 batch row per CTA) ----
    {
        float* hv  = sm->sx;
        float* red = sm->sx + 160;
        const int b = bid;   // 256 CTAs = 256 rows

        float v = __ldcg(&g_h1[(TN - 1) & 1][(size_t)tid * BN + b]);

        float sum = v;
#pragma unroll
        for (int o = 16; o; o >>= 1) sum += __shfl_xor_sync(0xffffffffu, sum, o);
        if ((tid & 31) == 0) red[tid >> 5] = sum;
        __syncthreads();
        float mu = (red[0] + red[1] + red[2] + red[3]) * (1.0f / HN);

        float d = v - mu;
        float q = d * d;
#pragma unroll
        for (int o = 16; o; o >>= 1) q += __shfl_xor_sync(0xffffffffu, q, o);
        __syncthreads();
        if ((tid & 31) == 0) red[tid >> 5] = q;
        __syncthreads();
        float var = (red[0] + red[1] + red[2] + red[3]) * (1.0f / HN);

        hv[tid] = d * rsqrtf(var + 1e-5f) * a.lng[tid] + a.lnb[tid];
        __syncthreads();

        if (tid < CN) {
            float acc = a.fcb[tid];
#pragma unroll 4
            for (int h = 0; h < HN; h++)
                acc = fmaf(hv[h], a.fcw[tid * HN + h], acc);
            a.out[b * CN + tid] = acc;
        }
    }
}

// ---------------------------------------------------------------------------
extern "C" void kernel_launch(void* const* d_in, const int* in_sizes, int n_in,
                              void* d_out, int out_size)
{
    LstmArgs a;
    a.x      = (const float*)d_in[0];
    a.length = (const int*)  d_in[1];
    a.Wih0 = (const float*)d_in[2];
    a.Whh0 = (const float*)d_in[3];
    a.bih0 = (const float*)d_in[4];
    a.bhh0 = (const float*)d_in[5];
    a.Wih1 = (const float*)d_in[6];
    a.Whh1 = (const float*)d_in[7];
    a.bih1 = (const float*)d_in[8];
    a.bhh1 = (const float*)d_in[9];
    a.lng  = (const float*)d_in[10];
    a.lnb  = (const float*)d_in[11];
    a.fcw  = (const float*)d_in[12];
    a.fcb  = (const float*)d_in[13];
    a.out  = (float*)d_out;

    static bool attr_done = false;
    if (!attr_done) {
        cudaFuncSetAttribute(lstm_kernel,
                             cudaFuncAttributeMaxDynamicSharedMemorySize,
                             SMEM_BYTES);
        attr_done = true;
    }

    lstm_kernel<<<NCTA, NTHR, SMEM_BYTES>>>(a);
}